// round 2
// baseline (speedup 1.0000x reference)
#include <cuda_runtime.h>
#include <math.h>

#define A_TOTAL 36864
#define NSORT   65536
#define NIN     6000
#define NOUTB   300
#define BATCH   4

// output layout (float32, concatenated reference tuple)
#define OFS_SCORES 0
#define OFS_LOCS   294912
#define OFS_ROIS   884736
#define OFS_RIDX   889536
#define OFS_ANCH   890736

// scratch (device globals; no allocation allowed)
__device__ float g_h[BATCH * 512 * 4096];
__device__ float g_boxes[BATCH * A_TOTAL * 4];
__device__ unsigned long long g_keys[BATCH * NSORT];
__device__ float g_bsort[BATCH * NIN * 4];
__device__ float g_areas[BATCH * NIN];
__device__ int   g_keep[BATCH * NIN];

// ---------------------------------------------------------------------------
// 3x3 conv 512->512, pad 1, + bias + relu.  Implicit GEMM:
// block = 128 out-channels x 64 pixels (one image row), K = 9 offsets x 512 cin
// ---------------------------------------------------------------------------
__global__ __launch_bounds__(256) void conv3x3_kernel(
    const float* __restrict__ x, const float* __restrict__ w,
    const float* __restrict__ bias)
{
    __shared__ float As[16][3][128];   // [ci][dx][co]
    __shared__ float Bs[16][66];       // [ci][x+1]

    const int m0  = blockIdx.x * 128;
    const int row = blockIdx.y;           // 0..255 -> (b, y)
    const int b   = row >> 6;
    const int y   = row & 63;
    const int tid = threadIdx.x;
    const int tx  = tid & 15;             // pixel group (4 px each)
    const int ty  = tid >> 4;             // co group (8 co each)

    float acc[8][4];
#pragma unroll
    for (int q = 0; q < 8; q++)
#pragma unroll
        for (int p = 0; p < 4; p++) acc[q][p] = 0.f;

    const float* xb = x + (size_t)b * 512 * 4096;

    for (int dy = 0; dy < 3; dy++) {
        const int yy = y + dy - 1;
        const bool yok = ((unsigned)yy < 64u);
        for (int cc = 0; cc < 512; cc += 16) {
            // load weights slice: w[co][cin][dy][dx]
            for (int idx = tid; idx < 128 * 16 * 3; idx += 256) {
                int co_l = idx / 48;
                int r    = idx - co_l * 48;
                int ci   = r / 3;
                int dx   = r - ci * 3;
                As[ci][dx][co_l] =
                    w[(((size_t)(m0 + co_l) * 512 + cc + ci) * 3 + dy) * 3 + dx];
            }
            // load input row slice (66 wide, zero-padded)
            for (int idx = tid; idx < 16 * 66; idx += 256) {
                int ci = idx / 66;
                int xx = idx - ci * 66;
                int xr = xx - 1;
                float v = 0.f;
                if (yok && (unsigned)xr < 64u)
                    v = xb[((cc + ci) * 64 + yy) * 64 + xr];
                Bs[ci][xx] = v;
            }
            __syncthreads();
#pragma unroll
            for (int dx = 0; dx < 3; dx++) {
#pragma unroll
                for (int ci = 0; ci < 16; ci++) {
                    float4 a0 = *(const float4*)&As[ci][dx][ty * 8];
                    float4 a1 = *(const float4*)&As[ci][dx][ty * 8 + 4];
                    float av[8] = {a0.x, a0.y, a0.z, a0.w, a1.x, a1.y, a1.z, a1.w};
                    float bv[4];
#pragma unroll
                    for (int p = 0; p < 4; p++) bv[p] = Bs[ci][dx + tx * 4 + p];
#pragma unroll
                    for (int q = 0; q < 8; q++)
#pragma unroll
                        for (int p = 0; p < 4; p++)
                            acc[q][p] += av[q] * bv[p];
                }
            }
            __syncthreads();
        }
    }

#pragma unroll
    for (int q = 0; q < 8; q++) {
        int co = m0 + ty * 8 + q;
        float bb = bias[co];
#pragma unroll
        for (int p = 0; p < 4; p++) {
            int px = tx * 4 + p;
            float v = acc[q][p] + bb;
            g_h[(((size_t)b * 512 + co) * 64 + y) * 64 + px] = v > 0.f ? v : 0.f;
        }
    }
}

// ---------------------------------------------------------------------------
// 1x1 heads (18 score + 36 loc channels) + softmax fg + box decode + sort keys
// one thread per pixel
// ---------------------------------------------------------------------------
__global__ __launch_bounds__(128) void heads_kernel(
    const float* __restrict__ sw, const float* __restrict__ sb,
    const float* __restrict__ lw, const float* __restrict__ lb,
    float* __restrict__ out)
{
    __shared__ float ws[64 * 54];
    const int tid = threadIdx.x;
    const int pg  = blockIdx.x * 128 + tid;   // 0..16383
    const int b   = pg >> 12;
    const int pix = pg & 4095;

    float acc[54];
#pragma unroll
    for (int c = 0; c < 54; c++) acc[c] = 0.f;

    for (int cc = 0; cc < 512; cc += 64) {
        for (int idx = tid; idx < 64 * 54; idx += 128) {
            int ci = idx / 54;
            int c  = idx - ci * 54;
            ws[idx] = (c < 18) ? sw[c * 512 + cc + ci]
                               : lw[(c - 18) * 512 + cc + ci];
        }
        __syncthreads();
#pragma unroll 4
        for (int ci = 0; ci < 64; ci++) {
            float v = g_h[((size_t)(b * 512 + cc + ci)) * 4096 + pix];
#pragma unroll
            for (int c = 0; c < 54; c++) acc[c] += v * ws[ci * 54 + c];
        }
        __syncthreads();
    }

    const int y  = pix >> 6;
    const int xq = pix & 63;
    const float sy = (float)(y * 16);
    const float sx = (float)(xq * 16);

#pragma unroll
    for (int k = 0; k < 9; k++) {
        // base anchors in double, rounded to fp32 (matches numpy)
        const double RR[3] = {0.5, 1.0, 2.0};
        const double SS[3] = {8.0, 16.0, 32.0};
        double r = RR[k / 3], s = SS[k % 3];
        double hh = 16.0 * s * sqrt(r);
        double wd = 16.0 * s * sqrt(1.0 / r);
        float by1 = (float)(8.0 - hh * 0.5), bx1 = (float)(8.0 - wd * 0.5);
        float by2 = (float)(8.0 + hh * 0.5), bx2 = (float)(8.0 + wd * 0.5);
        float ay1 = sy + by1, ax1 = sx + bx1, ay2 = sy + by2, ax2 = sx + bx2;

        const int a = pix * 9 + k;
        if (b == 0) {
            float* ap = out + OFS_ANCH + (size_t)a * 4;
            ap[0] = ay1; ap[1] = ax1; ap[2] = ay2; ap[3] = ax2;
        }

        float s0 = acc[k * 2 + 0] + sb[k * 2 + 0];
        float s1 = acc[k * 2 + 1] + sb[k * 2 + 1];
        out[OFS_SCORES + (size_t)b * 73728 + (size_t)a * 2 + 0] = s0;
        out[OFS_SCORES + (size_t)b * 73728 + (size_t)a * 2 + 1] = s1;

        float d0 = acc[18 + k * 4 + 0] + lb[k * 4 + 0];
        float d1 = acc[18 + k * 4 + 1] + lb[k * 4 + 1];
        float d2 = acc[18 + k * 4 + 2] + lb[k * 4 + 2];
        float d3 = acc[18 + k * 4 + 3] + lb[k * 4 + 3];
        float* lp = out + OFS_LOCS + (size_t)b * 147456 + (size_t)a * 4;
        lp[0] = d0; lp[1] = d1; lp[2] = d2; lp[3] = d3;

        // loc2bbox + clip
        float ah = ay2 - ay1, aw = ax2 - ax1;
        float cy = ay1 + 0.5f * ah, cx = ax1 + 0.5f * aw;
        float cty = d0 * ah + cy, ctx = d1 * aw + cx;
        float th = expf(d2) * ah, tw = expf(d3) * aw;
        float ry1 = cty - 0.5f * th, rx1 = ctx - 0.5f * tw;
        float ry2 = cty + 0.5f * th, rx2 = ctx + 0.5f * tw;
        float cy1 = fminf(fmaxf(ry1, 0.f), 1024.f);
        float cy2 = fminf(fmaxf(ry2, 0.f), 1024.f);
        float cx1 = fminf(fmaxf(rx1, 0.f), 1024.f);
        float cx2 = fminf(fmaxf(rx2, 0.f), 1024.f);
        bool valid = (cy2 - cy1 >= 16.f) && (cx2 - cx1 >= 16.f);

        // fg = softmax(...)[1] with max subtraction (matches jax.nn.softmax)
        float m = fmaxf(s0, s1);
        float e0 = expf(s0 - m), e1 = expf(s1 - m);
        float p1 = e1 / (e0 + e1);

        float* bp = g_boxes + ((size_t)b * A_TOTAL + a) * 4;
        bp[0] = cy1; bp[1] = cx1; bp[2] = cy2; bp[3] = cx2;

        // descending-score / ascending-index stable key (ascending sort)
        unsigned long long key;
        if (valid) {
            unsigned u = __float_as_uint(p1);
            u = (u & 0x80000000u) ? ~u : (u | 0x80000000u);
            key = ((unsigned long long)(~u) << 32) | (unsigned)a;
        } else {
            key = (0xFF800000ull << 32) | (unsigned)a;  // -inf score
        }
        g_keys[(size_t)b * NSORT + a] = key;
    }
}

// pad sort arrays to power of two with +inf keys
__global__ void pad_kernel()
{
    int i = blockIdx.x * 256 + threadIdx.x;   // 0..114687
    const int padn = NSORT - A_TOTAL;         // 28672
    int b = i / padn;
    int j = i - b * padn;
    if (b < BATCH)
        g_keys[(size_t)b * NSORT + A_TOTAL + j] = ~0ull;
}

// one block per batch: bitonic sort 65536 keys (ascending)
__global__ __launch_bounds__(1024) void sort_kernel()
{
    unsigned long long* keys = g_keys + (size_t)blockIdx.x * NSORT;
    for (int k = 2; k <= NSORT; k <<= 1) {
        for (int j = k >> 1; j > 0; j >>= 1) {
            for (int t = threadIdx.x; t < NSORT; t += 1024) {
                int ixj = t ^ j;
                if (ixj > t) {
                    unsigned long long a = keys[t], c = keys[ixj];
                    bool up = ((t & k) == 0);
                    if ((a > c) == up) { keys[t] = c; keys[ixj] = a; }
                }
            }
            __syncthreads();
        }
    }
}

// gather top-6000 boxes per batch in sorted order
__global__ void gather_kernel()
{
    int i = blockIdx.x * 256 + threadIdx.x;
    int b = blockIdx.y;
    if (i >= NIN) return;
    unsigned long long key = g_keys[(size_t)b * NSORT + i];
    unsigned idx = (unsigned)(key & 0xFFFFFFFFull);
    int valid = (key >> 63) == 0;
    float4 bx = *((const float4*)g_boxes + (size_t)b * A_TOTAL + idx);
    *((float4*)g_bsort + (size_t)b * NIN + i) = bx;
    g_areas[b * NIN + i] = (bx.z - bx.x) * (bx.w - bx.y);
    g_keep[b * NIN + i] = valid;
}

// sequential greedy NMS, one block per batch
__global__ __launch_bounds__(1024) void nms_kernel()
{
    const int b = blockIdx.x;
    const int tid = threadIdx.x;
    __shared__ unsigned char skeep[NIN];
    const float4* boxes = (const float4*)g_bsort + (size_t)b * NIN;
    const float*  areas = g_areas + b * NIN;

    for (int i = tid; i < NIN; i += 1024) skeep[i] = (unsigned char)g_keep[b * NIN + i];
    __syncthreads();

    for (int i = 0; i < NIN - 1; i++) {
        if (skeep[i]) {
            float4 bi = boxes[i];
            float ai = areas[i];
            for (int j = i + 1 + tid; j < NIN; j += 1024) {
                if (!skeep[j]) continue;
                float4 bj = boxes[j];
                float yy1 = fmaxf(bi.x, bj.x);
                float xx1 = fmaxf(bi.y, bj.y);
                float yy2 = fminf(bi.z, bj.z);
                float xx2 = fminf(bi.w, bj.w);
                float ih = fmaxf(yy2 - yy1, 0.f);
                float iw = fmaxf(xx2 - xx1, 0.f);
                float inter = ih * iw;
                float iou = inter / (ai + areas[j] - inter + 1e-9f);
                if (iou > 0.7f) skeep[j] = 0;
            }
            __syncthreads();
        }
    }
    for (int i = tid; i < NIN; i += 1024) g_keep[b * NIN + i] = skeep[i];
}

// compact kept boxes into first 300 rows; zero-fill the rest; roi_indices
__global__ __launch_bounds__(1024) void compact_kernel(float* __restrict__ out)
{
    const int b = blockIdx.x;
    const int tid = threadIdx.x;
    __shared__ int csum[1024];

    const int base = tid * 6;           // 1024*6 = 6144 >= 6000
    int local[6];
    int cnt = 0;
#pragma unroll
    for (int e = 0; e < 6; e++) {
        int i = base + e;
        int k = (i < NIN) ? g_keep[b * NIN + i] : 0;
        local[e] = k;
        cnt += k;
    }
    csum[tid] = cnt;
    __syncthreads();
    for (int off = 1; off < 1024; off <<= 1) {
        int v = (tid >= off) ? csum[tid - off] : 0;
        __syncthreads();
        csum[tid] += v;
        __syncthreads();
    }
    int rank = csum[tid] - cnt;   // exclusive prefix

    float* rois = out + OFS_ROIS + (size_t)b * 1200;
    for (int i = tid; i < 1200; i += 1024) rois[i] = 0.f;
    float* ridx = out + OFS_RIDX + (size_t)b * 300;
    for (int i = tid; i < 300; i += 1024) ridx[i] = (float)b;
    __syncthreads();

    int r = rank;
#pragma unroll
    for (int e = 0; e < 6; e++) {
        int i = base + e;
        if (i < NIN && local[e]) {
            if (r < NOUTB) {
                float4 bx = *((const float4*)g_bsort + (size_t)b * NIN + i);
                rois[r * 4 + 0] = bx.x;
                rois[r * 4 + 1] = bx.y;
                rois[r * 4 + 2] = bx.z;
                rois[r * 4 + 3] = bx.w;
            }
            r++;
        }
    }
}

extern "C" void kernel_launch(void* const* d_in, const int* in_sizes, int n_in,
                              void* d_out, int out_size)
{
    const float* x       = (const float*)d_in[0];
    const float* conv_w  = (const float*)d_in[1];
    const float* conv_b  = (const float*)d_in[2];
    const float* score_w = (const float*)d_in[3];
    const float* score_b = (const float*)d_in[4];
    const float* loc_w   = (const float*)d_in[5];
    const float* loc_b   = (const float*)d_in[6];
    float* out = (float*)d_out;

    conv3x3_kernel<<<dim3(4, 256), 256>>>(x, conv_w, conv_b);
    heads_kernel<<<128, 128>>>(score_w, score_b, loc_w, loc_b, out);
    pad_kernel<<<448, 256>>>();
    sort_kernel<<<BATCH, 1024>>>();
    gather_kernel<<<dim3(24, BATCH), 256>>>();
    nms_kernel<<<BATCH, 1024>>>();
    compact_kernel<<<BATCH, 1024>>>(out);
}

// round 6
// speedup vs baseline: 1.4321x; 1.4321x over previous
#include <cuda_runtime.h>
#include <math.h>

#define A_TOTAL 36864
#define NIN     6000
#define NOUTB   300
#define BATCH   4
#define NSEL    16384

// output layout (float32, concatenated reference tuple)
#define OFS_SCORES 0
#define OFS_LOCS   294912
#define OFS_ROIS   884736
#define OFS_RIDX   889536
#define OFS_ANCH   890736

// scratch (device globals; no allocation allowed)
__device__ float  g_h[BATCH * 512 * 4096];
__device__ float  g_wt[9 * 512 * 512];          // [dy*3+dx][ci][co]
__device__ float4 g_boxes4[BATCH * A_TOTAL];
__device__ unsigned long long g_keys[BATCH * A_TOTAL];
__device__ unsigned g_hist[BATCH * 65536];
__device__ int    g_thr[BATCH];
__device__ int    g_cnt[BATCH];
__device__ unsigned long long g_sel[BATCH * NSEL];
__device__ float4 g_bsort4[BATCH * NIN];
__device__ float  g_areas[BATCH * NIN];
__device__ int    g_keep[BATCH * NIN];

// ---------------------------------------------------------------------------
// weight transpose: w[co][ci][dy][dx] -> g_wt[(dy*3+dx)][ci][co]
// ---------------------------------------------------------------------------
__global__ void wtrans_kernel(const float* __restrict__ w)
{
    int idx = blockIdx.x * 1024 + threadIdx.x;   // 0 .. 2359295
    int co = idx & 511;
    int ci = (idx >> 9) & 511;
    int kk = idx >> 18;                           // dy*3+dx, 0..8
    g_wt[(kk * 512 + ci) * 512 + co] = w[(co * 512 + ci) * 9 + kk];
}

__global__ void zerohist_kernel()
{
    g_hist[blockIdx.x * 1024 + threadIdx.x] = 0u;
}

// ---------------------------------------------------------------------------
// 3x3 conv 512->512 + bias + relu, packed f32x2 FMA.
// block: 128 out-channels x 128 px (2 rows).  thread: 8 co (4 pairs) x 8 px.
// ---------------------------------------------------------------------------
__global__ __launch_bounds__(256, 2) void conv3x3_kernel(
    const float* __restrict__ x, const float* __restrict__ bias)
{
    __shared__ __align__(16) float As[3 * 16 * 128];  // [dx][ci][co]
    __shared__ __align__(16) float Bs[16 * 2 * 68];   // [ci][rr][x+1] (pad 68)

    const int m0  = blockIdx.x * 128;
    const int b   = blockIdx.y >> 5;
    const int ry  = blockIdx.y & 31;
    const int y0  = ry * 2;
    const int tid = threadIdx.x;
    const int tx  = tid & 15;
    const int ty  = tid >> 4;
    const int r   = tx >> 3;          // output row within pair
    const int px0 = (tx & 7) * 8;     // 8 consecutive px

    unsigned long long acc[4][8];
#pragma unroll
    for (int q = 0; q < 4; q++)
#pragma unroll
        for (int p = 0; p < 8; p++) acc[q][p] = 0ull;

    const float* xb = x + (size_t)b * 512 * 4096;

    for (int dy = 0; dy < 3; dy++) {
        for (int cc = 0; cc < 512; cc += 16) {
            // stage weights: conflict-free, coalesced
            for (int idx = tid; idx < 6144; idx += 256) {
                int dx = idx >> 11;
                int ci = (idx >> 7) & 15;
                int co = idx & 127;
                As[(dx * 16 + ci) * 128 + co] =
                    g_wt[(((dy * 3 + dx) * 512) + cc + ci) * 512 + m0 + co];
            }
            // stage 2 input rows (zero-padded, 66 valid cols, stride 68)
            for (int idx = tid; idx < 2112; idx += 256) {
                int ci = idx / 132;
                int rem = idx - ci * 132;
                int rr = rem / 66;
                int xx = rem - rr * 66;
                int yy = y0 + rr + dy - 1;
                int xr = xx - 1;
                float v = 0.f;
                if ((unsigned)yy < 64u && (unsigned)xr < 64u)
                    v = xb[((cc + ci) * 64 + yy) * 64 + xr];
                Bs[(ci * 2 + rr) * 68 + xx] = v;
            }
            __syncthreads();
#pragma unroll
            for (int ci = 0; ci < 16; ci++) {
                const float* brow = &Bs[(ci * 2 + r) * 68];
                float4 b0 = *(const float4*)(brow + px0);
                float4 b1 = *(const float4*)(brow + px0 + 4);
                float bv[10];
                bv[0] = b0.x; bv[1] = b0.y; bv[2] = b0.z; bv[3] = b0.w;
                bv[4] = b1.x; bv[5] = b1.y; bv[6] = b1.z; bv[7] = b1.w;
                bv[8] = brow[px0 + 8]; bv[9] = brow[px0 + 9];
                unsigned long long bb[10];
#pragma unroll
                for (int p = 0; p < 10; p++)
                    asm("mov.b64 %0, {%1, %1};" : "=l"(bb[p]) : "f"(bv[p]));
#pragma unroll
                for (int dx = 0; dx < 3; dx++) {
                    const float* arow = &As[(dx * 16 + ci) * 128 + ty * 8];
                    ulonglong2 A01 = *(const ulonglong2*)(arow);
                    ulonglong2 A23 = *(const ulonglong2*)(arow + 4);
                    unsigned long long a2[4] = {A01.x, A01.y, A23.x, A23.y};
#pragma unroll
                    for (int q = 0; q < 4; q++)
#pragma unroll
                        for (int p = 0; p < 8; p++)
                            asm("fma.rn.f32x2 %0, %1, %2, %0;"
                                : "+l"(acc[q][p]) : "l"(a2[q]), "l"(bb[dx + p]));
                }
            }
            __syncthreads();
        }
    }

    const int yout = y0 + r;
#pragma unroll
    for (int q = 0; q < 4; q++) {
        int co0 = m0 + ty * 8 + q * 2;
        float bb0 = bias[co0], bb1 = bias[co0 + 1];
        float v0[8], v1[8];
#pragma unroll
        for (int p = 0; p < 8; p++) {
            unsigned lo = (unsigned)acc[q][p];
            unsigned hi = (unsigned)(acc[q][p] >> 32);
            float a = __uint_as_float(lo) + bb0;
            float c = __uint_as_float(hi) + bb1;
            v0[p] = a > 0.f ? a : 0.f;
            v1[p] = c > 0.f ? c : 0.f;
        }
        float* d0 = g_h + ((((size_t)b * 512 + co0) * 64 + yout) * 64 + px0);
        float* d1 = g_h + ((((size_t)b * 512 + co0 + 1) * 64 + yout) * 64 + px0);
        *(float4*)(d0)     = make_float4(v0[0], v0[1], v0[2], v0[3]);
        *(float4*)(d0 + 4) = make_float4(v0[4], v0[5], v0[6], v0[7]);
        *(float4*)(d1)     = make_float4(v1[0], v1[1], v1[2], v1[3]);
        *(float4*)(d1 + 4) = make_float4(v1[4], v1[5], v1[6], v1[7]);
    }
}

// ---------------------------------------------------------------------------
// 1x1 heads + softmax fg + box decode + sort keys + score-bucket histogram
// ---------------------------------------------------------------------------
__global__ __launch_bounds__(128) void heads_kernel(
    const float* __restrict__ sw, const float* __restrict__ sb,
    const float* __restrict__ lw, const float* __restrict__ lb,
    float* __restrict__ out)
{
    __shared__ float ws[64 * 54];
    const int tid = threadIdx.x;
    const int pg  = blockIdx.x * 128 + tid;
    const int b   = pg >> 12;
    const int pix = pg & 4095;

    float acc[54];
#pragma unroll
    for (int c = 0; c < 54; c++) acc[c] = 0.f;

    for (int cc = 0; cc < 512; cc += 64) {
        for (int idx = tid; idx < 64 * 54; idx += 128) {
            int ci = idx / 54;
            int c  = idx - ci * 54;
            ws[idx] = (c < 18) ? sw[c * 512 + cc + ci]
                               : lw[(c - 18) * 512 + cc + ci];
        }
        __syncthreads();
#pragma unroll 4
        for (int ci = 0; ci < 64; ci++) {
            float v = g_h[((size_t)(b * 512 + cc + ci)) * 4096 + pix];
#pragma unroll
            for (int c = 0; c < 54; c++) acc[c] += v * ws[ci * 54 + c];
        }
        __syncthreads();
    }

    const int y  = pix >> 6;
    const int xq = pix & 63;
    const float sy = (float)(y * 16);
    const float sx = (float)(xq * 16);

#pragma unroll
    for (int k = 0; k < 9; k++) {
        const double RR[3] = {0.5, 1.0, 2.0};
        const double SS[3] = {8.0, 16.0, 32.0};
        double rr = RR[k / 3], ss = SS[k % 3];
        double hh = 16.0 * ss * sqrt(rr);
        double wd = 16.0 * ss * sqrt(1.0 / rr);
        float by1 = (float)(8.0 - hh * 0.5), bx1 = (float)(8.0 - wd * 0.5);
        float by2 = (float)(8.0 + hh * 0.5), bx2 = (float)(8.0 + wd * 0.5);
        float ay1 = sy + by1, ax1 = sx + bx1, ay2 = sy + by2, ax2 = sx + bx2;

        const int a = pix * 9 + k;
        if (b == 0) {
            float* ap = out + OFS_ANCH + (size_t)a * 4;
            ap[0] = ay1; ap[1] = ax1; ap[2] = ay2; ap[3] = ax2;
        }

        float s0 = acc[k * 2 + 0] + sb[k * 2 + 0];
        float s1 = acc[k * 2 + 1] + sb[k * 2 + 1];
        out[OFS_SCORES + (size_t)b * 73728 + (size_t)a * 2 + 0] = s0;
        out[OFS_SCORES + (size_t)b * 73728 + (size_t)a * 2 + 1] = s1;

        float d0 = acc[18 + k * 4 + 0] + lb[k * 4 + 0];
        float d1 = acc[18 + k * 4 + 1] + lb[k * 4 + 1];
        float d2 = acc[18 + k * 4 + 2] + lb[k * 4 + 2];
        float d3 = acc[18 + k * 4 + 3] + lb[k * 4 + 3];
        float* lp = out + OFS_LOCS + (size_t)b * 147456 + (size_t)a * 4;
        lp[0] = d0; lp[1] = d1; lp[2] = d2; lp[3] = d3;

        float ah = ay2 - ay1, aw = ax2 - ax1;
        float cy = ay1 + 0.5f * ah, cx = ax1 + 0.5f * aw;
        float cty = d0 * ah + cy, ctx = d1 * aw + cx;
        float th = expf(d2) * ah, tw = expf(d3) * aw;
        float cy1 = fminf(fmaxf(cty - 0.5f * th, 0.f), 1024.f);
        float cy2 = fminf(fmaxf(cty + 0.5f * th, 0.f), 1024.f);
        float cx1 = fminf(fmaxf(ctx - 0.5f * tw, 0.f), 1024.f);
        float cx2 = fminf(fmaxf(ctx + 0.5f * tw, 0.f), 1024.f);
        bool valid = (cy2 - cy1 >= 16.f) && (cx2 - cx1 >= 16.f);

        float m = fmaxf(s0, s1);
        float e0 = expf(s0 - m), e1 = expf(s1 - m);
        float p1 = e1 / (e0 + e1);

        g_boxes4[(size_t)b * A_TOTAL + a] = make_float4(cy1, cx1, cy2, cx2);

        unsigned long long key;
        if (valid) {
            unsigned u = __float_as_uint(p1);
            u = (u & 0x80000000u) ? ~u : (u | 0x80000000u);
            key = ((unsigned long long)(~u) << 32) | (unsigned)a;
        } else {
            key = (0xFF800000ull << 32) | (unsigned)a;  // -inf score
        }
        g_keys[(size_t)b * A_TOTAL + a] = key;
        atomicAdd(&g_hist[b * 65536 + (unsigned)(key >> 48)], 1u);
    }
}

// find bucket threshold covering rank NIN; also reset count + pad sel buffer
__global__ __launch_bounds__(1024) void select_kernel()
{
    const int b = blockIdx.x, tid = threadIdx.x;
    __shared__ int part[1024];
    const unsigned* h = g_hist + b * 65536;
    int s = 0;
    for (int k = 0; k < 64; k++) s += (int)h[tid * 64 + k];
    part[tid] = s;
    __syncthreads();
    for (int off = 1; off < 1024; off <<= 1) {
        int v = (tid >= off) ? part[tid - off] : 0;
        __syncthreads();
        part[tid] += v;
        __syncthreads();
    }
    int incl = part[tid];
    int excl = incl - s;
    if (excl < NIN && incl >= NIN) {
        int c = excl, T = tid * 64 + 63;
        for (int k = 0; k < 64; k++) {
            c += (int)h[tid * 64 + k];
            if (c >= NIN) { T = tid * 64 + k; break; }
        }
        g_thr[b] = T;
    }
    if (tid == 0) g_cnt[b] = 0;
    for (int i = tid; i < NSEL; i += 1024) g_sel[b * NSEL + i] = ~0ull;
}

__global__ void compact_sel_kernel()
{
    int i = blockIdx.x * 256 + threadIdx.x;
    int b = blockIdx.y;
    if (i >= A_TOTAL) return;
    unsigned long long key = g_keys[(size_t)b * A_TOTAL + i];
    if ((int)(unsigned)(key >> 48) <= g_thr[b]) {
        int p = atomicAdd(&g_cnt[b], 1);
        if (p < NSEL) g_sel[b * NSEL + p] = key;
    }
}

// per-batch smem bitonic sort of <=16384 selected keys, then gather top-6000
__global__ __launch_bounds__(1024) void sortsel_kernel()
{
    const int b = blockIdx.x, tid = threadIdx.x;
    extern __shared__ unsigned long long s[];
    for (int i = tid; i < NSEL; i += 1024) s[i] = g_sel[b * NSEL + i];
    __syncthreads();
    for (int k = 2; k <= NSEL; k <<= 1) {
        for (int j = k >> 1; j > 0; j >>= 1) {
            for (int t = tid; t < NSEL; t += 1024) {
                int ixj = t ^ j;
                if (ixj > t) {
                    unsigned long long A = s[t], B = s[ixj];
                    bool up = ((t & k) == 0);
                    if ((A > B) == up) { s[t] = B; s[ixj] = A; }
                }
            }
            __syncthreads();
        }
    }
    for (int i = tid; i < NIN; i += 1024) {
        unsigned long long key = s[i];
        unsigned idx = (unsigned)key;
        float4 bx = g_boxes4[(size_t)b * A_TOTAL + idx];
        g_bsort4[b * NIN + i] = bx;
        g_areas[b * NIN + i] = (bx.z - bx.x) * (bx.w - bx.y);
        g_keep[b * NIN + i] = (int)((key >> 63) == 0);
    }
}

// sequential greedy NMS, all-smem + register-resident owned boxes
__global__ __launch_bounds__(1024) void nms_kernel()
{
    const int b = blockIdx.x, tid = threadIdx.x;
    extern __shared__ char nsm[];
    float4* bsh = (float4*)nsm;                          // 96000 B
    float* ash = (float*)(nsm + 96000);                  // 24000 B
    unsigned char* ksh = (unsigned char*)(nsm + 120000); // 6000 B

    for (int i = tid; i < NIN; i += 1024) {
        bsh[i] = g_bsort4[b * NIN + i];
        ash[i] = g_areas[b * NIN + i];
        ksh[i] = (unsigned char)g_keep[b * NIN + i];
    }
    __syncthreads();

    float4 myb[6]; float mya[6]; int myk[6];
#pragma unroll
    for (int e = 0; e < 6; e++) {
        int j = tid * 6 + e;
        if (j < NIN) { myb[e] = bsh[j]; mya[e] = ash[j]; myk[e] = (int)ksh[j]; }
        else myk[e] = 0;
    }

    for (int i = 0; i < NIN - 1; i++) {
        if (ksh[i]) {
            float4 bi = bsh[i];
            float ai = ash[i];
#pragma unroll
            for (int e = 0; e < 6; e++) {
                int j = tid * 6 + e;
                if (myk[e] && j > i) {
                    float yy1 = fmaxf(bi.x, myb[e].x);
                    float xx1 = fmaxf(bi.y, myb[e].y);
                    float yy2 = fminf(bi.z, myb[e].z);
                    float xx2 = fminf(bi.w, myb[e].w);
                    float inter = fmaxf(yy2 - yy1, 0.f) * fmaxf(xx2 - xx1, 0.f);
                    float iou = inter / (ai + mya[e] - inter + 1e-9f);
                    if (iou > 0.7f) { myk[e] = 0; ksh[j] = 0; }
                }
            }
            __syncthreads();
        }
    }
    for (int i = tid; i < NIN; i += 1024) g_keep[b * NIN + i] = (int)ksh[i];
}

// compact kept boxes into first 300 rows; zero-fill the rest; roi_indices
__global__ __launch_bounds__(1024) void compact_kernel(float* __restrict__ out)
{
    const int b = blockIdx.x;
    const int tid = threadIdx.x;
    __shared__ int csum[1024];

    const int base = tid * 6;
    int local[6];
    int cnt = 0;
#pragma unroll
    for (int e = 0; e < 6; e++) {
        int i = base + e;
        int k = (i < NIN) ? g_keep[b * NIN + i] : 0;
        local[e] = k;
        cnt += k;
    }
    csum[tid] = cnt;
    __syncthreads();
    for (int off = 1; off < 1024; off <<= 1) {
        int v = (tid >= off) ? csum[tid - off] : 0;
        __syncthreads();
        csum[tid] += v;
        __syncthreads();
    }
    int rank = csum[tid] - cnt;

    float* rois = out + OFS_ROIS + (size_t)b * 1200;
    for (int i = tid; i < 1200; i += 1024) rois[i] = 0.f;
    float* ridx = out + OFS_RIDX + (size_t)b * 300;
    for (int i = tid; i < 300; i += 1024) ridx[i] = (float)b;
    __syncthreads();

    int r = rank;
#pragma unroll
    for (int e = 0; e < 6; e++) {
        int i = base + e;
        if (i < NIN && local[e]) {
            if (r < NOUTB) {
                float4 bx = g_bsort4[b * NIN + i];
                rois[r * 4 + 0] = bx.x;
                rois[r * 4 + 1] = bx.y;
                rois[r * 4 + 2] = bx.z;
                rois[r * 4 + 3] = bx.w;
            }
            r++;
        }
    }
}

extern "C" void kernel_launch(void* const* d_in, const int* in_sizes, int n_in,
                              void* d_out, int out_size)
{
    const float* x       = (const float*)d_in[0];
    const float* conv_w  = (const float*)d_in[1];
    const float* conv_b  = (const float*)d_in[2];
    const float* score_w = (const float*)d_in[3];
    const float* score_b = (const float*)d_in[4];
    const float* loc_w   = (const float*)d_in[5];
    const float* loc_b   = (const float*)d_in[6];
    float* out = (float*)d_out;

    cudaFuncSetAttribute(sortsel_kernel,
        cudaFuncAttributeMaxDynamicSharedMemorySize, NSEL * 8);
    cudaFuncSetAttribute(nms_kernel,
        cudaFuncAttributeMaxDynamicSharedMemorySize, 126016);

    wtrans_kernel<<<2304, 1024>>>(conv_w);
    zerohist_kernel<<<256, 1024>>>();
    conv3x3_kernel<<<dim3(4, 128), 256>>>(x, conv_b);
    heads_kernel<<<128, 128>>>(score_w, score_b, loc_w, loc_b, out);
    select_kernel<<<BATCH, 1024>>>();
    compact_sel_kernel<<<dim3(144, BATCH), 256>>>();
    sortsel_kernel<<<BATCH, 1024, NSEL * 8>>>();
    nms_kernel<<<BATCH, 1024, 126016>>>();
    compact_kernel<<<BATCH, 1024>>>(out);
}